// round 7
// baseline (speedup 1.0000x reference)
#include <cuda_runtime.h>
#include <math.h>

#define N_TOK   16384
#define D_MODEL 2048
#define Q_DIM   512
#define H_HEADS 4
#define HQ      2048      // H * Q
#define HALF    256       // Q/2
#define S_KEYS  256
#define TOPK    4
#define BN_EPS  1e-5f
#define NEG_BIG (-1e30f)
#define NPART   4         // row partials in stats reduction (XLA-style)
#define CHUNK   (N_TOK / NPART)   // 4096 rows per partial

// -------------------- device scratch (static, no allocation) --------------------
static __device__ float  g_q [(size_t)N_TOK * HQ];   // raw query projections [N, H*Q]
static __device__ float  g_s [(size_t)N_TOK * HQ];   // scores [N, H, 2, 256]
static __device__ float  g_pm[NPART][HQ];            // mean partials
static __device__ float  g_pv[NPART][HQ];            // var partials
static __device__ float  g_mun[HQ];                  // BN mean
static __device__ float  g_rn [HQ];                  // rsqrtf(var+eps)
static __device__ float  g_Kt [2 * HALF * S_KEYS];   // Kt[tbl][c][k] = K[k][c]

// =====================================================================
// Kernel 1: q = x @ Wq + bq.  128x128 tile, BK=16, 256 thr, 8x8/thread.
// ASCENDING k, single FMA chain per accumulator (mirrors cuBLAS SGEMM
// reduction order). Register-prefetch pipeline (doesn't change FP order).
// =====================================================================
__global__ __launch_bounds__(256) void k_gemm_q(
    const float* __restrict__ x, const float* __restrict__ Wq, const float* __restrict__ bq)
{
    __shared__ float As[16][128];
    __shared__ float Bs[16][128];

    const int tid = threadIdx.x;          // 0..255
    const int tx  = tid & 15;             // col group: 8 cols each
    const int ty  = tid >> 4;             // row group: 8 rows each

    const int rowTile = blockIdx.x;       // 0..127
    const int colTile = blockIdx.y;       // 0..15
    const int head    = colTile >> 2;
    const int cih     = (colTile & 3) * 128;

    const float* A = x  + (size_t)rowTile * 128 * D_MODEL;
    const float* B = Wq + (size_t)head * D_MODEL * Q_DIM + cih;

    float acc[8][8];
    #pragma unroll
    for (int i = 0; i < 8; i++)
        #pragma unroll
        for (int j = 0; j < 8; j++) acc[i][j] = 0.0f;

    int a_r[2], a_c[2], b_r[2], b_c[2];
    #pragma unroll
    for (int i = 0; i < 2; i++) {
        int id = tid + i * 256;           // 0..511
        a_r[i] = id >> 2;                 // A row 0..127
        a_c[i] = (id & 3) * 4;            // A k 0,4,8,12
        b_r[i] = id >> 5;                 // B k 0..15
        b_c[i] = (id & 31) * 4;           // B col
    }

    float4 pa[2], pb[2];
    int kt = 0;
    #pragma unroll
    for (int i = 0; i < 2; i++) {
        pa[i] = *(const float4*)(A + (size_t)a_r[i] * D_MODEL + kt + a_c[i]);
        pb[i] = *(const float4*)(B + (size_t)(kt + b_r[i]) * Q_DIM + b_c[i]);
    }

    while (kt < D_MODEL) {
        #pragma unroll
        for (int i = 0; i < 2; i++) {
            As[a_c[i] + 0][a_r[i]] = pa[i].x;
            As[a_c[i] + 1][a_r[i]] = pa[i].y;
            As[a_c[i] + 2][a_r[i]] = pa[i].z;
            As[a_c[i] + 3][a_r[i]] = pa[i].w;
            *(float4*)(&Bs[b_r[i]][b_c[i]]) = pb[i];
        }
        __syncthreads();

        int ktn = kt + 16;
        if (ktn < D_MODEL) {
            #pragma unroll
            for (int i = 0; i < 2; i++) {
                pa[i] = *(const float4*)(A + (size_t)a_r[i] * D_MODEL + ktn + a_c[i]);
                pb[i] = *(const float4*)(B + (size_t)(ktn + b_r[i]) * Q_DIM + b_c[i]);
            }
        }

        #pragma unroll
        for (int k = 0; k < 16; k++) {
            float a[8], b[8];
            #pragma unroll
            for (int i = 0; i < 8; i++) a[i] = As[k][ty * 8 + i];
            #pragma unroll
            for (int j = 0; j < 8; j++) b[j] = Bs[k][tx * 8 + j];
            #pragma unroll
            for (int i = 0; i < 8; i++)
                #pragma unroll
                for (int j = 0; j < 8; j++)
                    acc[i][j] = fmaf(a[i], b[j], acc[i][j]);
        }
        __syncthreads();
        kt = ktn;
    }

    float* C = g_q + (size_t)rowTile * 128 * HQ + colTile * 128;
    const float* bias = bq + head * Q_DIM + cih;
    #pragma unroll
    for (int i = 0; i < 8; i++) {
        int r = ty * 8 + i;
        #pragma unroll
        for (int j = 0; j < 8; j++) {
            int c = tx * 8 + j;
            C[(size_t)r * HQ + c] = acc[i][j] + bias[c];
        }
    }
}

// =====================================================================
// Kernel 2a: MEAN partials, XLA-GPU column-reduction shape.
// Partial b covers rows [b*4096, (b+1)*4096): lane handles rows
// b*4096 + lane + 32*j, j ascending 0..127 (fp32 chain), then 32-lane
// shfl-down tree. One warp per (column, partial).
// =====================================================================
__global__ __launch_bounds__(256) void k_mean_part()
{
    int c    = blockIdx.x * 8 + (threadIdx.x >> 5);   // 0..2047
    int b    = blockIdx.y;                             // 0..3
    int lane = threadIdx.x & 31;
    float s = 0.0f;
    const float* p = g_q + ((size_t)b * CHUNK + lane) * HQ + c;
    for (int j = 0; j < CHUNK / 32; j++)
        s = __fadd_rn(s, p[(size_t)j * 32 * HQ]);
    #pragma unroll
    for (int off = 16; off > 0; off >>= 1)
        s = __fadd_rn(s, __shfl_down_sync(0xffffffffu, s, off));
    if (lane == 0) g_pm[b][c] = s;
}

__global__ __launch_bounds__(256) void k_mean_fin()
{
    int c = blockIdx.x * 256 + threadIdx.x;
    float s = g_pm[0][c];
    #pragma unroll
    for (int b = 1; b < NPART; b++) s = __fadd_rn(s, g_pm[b][c]);
    g_mun[c] = s * (1.0f / (float)N_TOK);   // /2^14 exact
}

// =====================================================================
// Kernel 2b: VAR partials via mean((x-mu)^2), same reduction shape,
// explicit sub/mul/add (no FMA contraction). Then rn = rsqrtf(var+eps).
// =====================================================================
__global__ __launch_bounds__(256) void k_var_part()
{
    int c    = blockIdx.x * 8 + (threadIdx.x >> 5);
    int b    = blockIdx.y;
    int lane = threadIdx.x & 31;
    float mu = g_mun[c];
    float s = 0.0f;
    const float* p = g_q + ((size_t)b * CHUNK + lane) * HQ + c;
    for (int j = 0; j < CHUNK / 32; j++) {
        float d = __fsub_rn(p[(size_t)j * 32 * HQ], mu);
        s = __fadd_rn(s, __fmul_rn(d, d));
    }
    #pragma unroll
    for (int off = 16; off > 0; off >>= 1)
        s = __fadd_rn(s, __shfl_down_sync(0xffffffffu, s, off));
    if (lane == 0) g_pv[b][c] = s;
}

__global__ __launch_bounds__(256) void k_var_fin()
{
    int c = blockIdx.x * 256 + threadIdx.x;
    float s = g_pv[0][c];
    #pragma unroll
    for (int b = 1; b < NPART; b++) s = __fadd_rn(s, g_pv[b][c]);
    float var = s * (1.0f / (float)N_TOK);
    g_rn[c] = rsqrtf(__fadd_rn(var, BN_EPS));
}

// =====================================================================
// Kernel 3: transpose key tables. Kt[tbl][c][k] = K[k][c].
// =====================================================================
__global__ __launch_bounds__(256) void k_transpose(
    const float* __restrict__ K1, const float* __restrict__ K2)
{
    int idx = blockIdx.x * 256 + threadIdx.x;     // 0 .. 2*256*256-1
    int tbl = idx >> 16;
    int c   = (idx >> 8) & 255;
    int k   = idx & 255;
    const float* Ksrc = tbl ? K2 : K1;
    g_Kt[idx] = Ksrc[k * HALF + c];
}

// =====================================================================
// Kernel 4: scoring GEMM  s = normalize(q) @ Kt.
// Normalization on A-tile load, exact reference elementwise order:
//   ((q - mu) * rsqrt) * gamma + beta  (fp32; gamma=1, beta=0 -> exact).
// ASCENDING k single FMA chain. 512 thr, 4x8/thread.
// =====================================================================
__global__ __launch_bounds__(512) void k_gemm_s(
    const float* __restrict__ gamma, const float* __restrict__ beta)
{
    __shared__ float As[16][128];
    __shared__ float Bs[16][128];

    const int tid = threadIdx.x;
    const int tx  = tid & 15;
    const int ty  = tid >> 4;

    const int z   = blockIdx.z;     // 0..7
    const int tbl = z >> 2;
    const int h   = z & 3;
    const int cb  = h * Q_DIM + tbl * HALF;

    const float* A  = g_q + (size_t)blockIdx.x * 128 * HQ + cb;
    const float* B  = g_Kt + (size_t)tbl * HALF * S_KEYS + blockIdx.y * 128;
    const float* mu = g_mun + cb;
    const float* rn = g_rn  + cb;
    const float* gm = gamma + cb;
    const float* bt = beta  + cb;

    float acc[4][8];
    #pragma unroll
    for (int i = 0; i < 4; i++)
        #pragma unroll
        for (int j = 0; j < 8; j++) acc[i][j] = 0.0f;

    const int ar = tid >> 2;
    const int ac = (tid & 3) * 4;
    const int br = tid >> 5;
    const int bc = (tid & 31) * 4;

    for (int kt = 0; kt < HALF; kt += 16) {
        float4 va = *(const float4*)(A + (size_t)ar * HQ + kt + ac);
        int c0 = kt + ac;
        va.x = __fmul_rn(__fsub_rn(va.x, mu[c0 + 0]), rn[c0 + 0]) * gm[c0 + 0] + bt[c0 + 0];
        va.y = __fmul_rn(__fsub_rn(va.y, mu[c0 + 1]), rn[c0 + 1]) * gm[c0 + 1] + bt[c0 + 1];
        va.z = __fmul_rn(__fsub_rn(va.z, mu[c0 + 2]), rn[c0 + 2]) * gm[c0 + 2] + bt[c0 + 2];
        va.w = __fmul_rn(__fsub_rn(va.w, mu[c0 + 3]), rn[c0 + 3]) * gm[c0 + 3] + bt[c0 + 3];
        As[ac + 0][ar] = va.x; As[ac + 1][ar] = va.y;
        As[ac + 2][ar] = va.z; As[ac + 3][ar] = va.w;
        *(float4*)(&Bs[br][bc]) = *(const float4*)(B + (size_t)(kt + br) * S_KEYS + bc);
        __syncthreads();

        #pragma unroll
        for (int k = 0; k < 16; k++) {
            float a[4], b[8];
            #pragma unroll
            for (int i = 0; i < 4; i++) a[i] = As[k][ty * 4 + i];
            #pragma unroll
            for (int j = 0; j < 8; j++) b[j] = Bs[k][tx * 8 + j];
            #pragma unroll
            for (int i = 0; i < 4; i++)
                #pragma unroll
                for (int j = 0; j < 8; j++)
                    acc[i][j] = fmaf(a[i], b[j], acc[i][j]);
        }
        __syncthreads();
    }

    float* C = g_s + (size_t)blockIdx.x * 128 * HQ + cb + blockIdx.y * 128;
    #pragma unroll
    for (int i = 0; i < 4; i++) {
        int r = ty * 4 + i;
        #pragma unroll
        for (int j = 0; j < 8; j++) {
            int c = tx * 8 + j;
            C[(size_t)r * HQ + c] = acc[i][j];
        }
    }
}

// =====================================================================
// Kernel 5: per-(n,h) two-stage top-k + softmax. One warp per row.
// Ties break to lower index (matching jax.lax.top_k).
// =====================================================================
__global__ __launch_bounds__(256) void k_topk(float* __restrict__ out)
{
    int gw   = (blockIdx.x * blockDim.x + threadIdx.x) >> 5;  // n*H + h
    int lane = threadIdx.x & 31;
    if (gw >= N_TOK * H_HEADS) return;
    int n = gw >> 2;
    int h = gw & 3;

    const float* s1 = g_s + (size_t)n * HQ + h * Q_DIM;
    const float* s2 = s1 + HALF;

    float v1[8], v2[8];
    #pragma unroll
    for (int t = 0; t < 8; t++) { v1[t] = s1[t * 32 + lane]; v2[t] = s2[t * 32 + lane]; }

    float tv1[8], tv2[8];
    int   ti1[8], ti2[8];

    #pragma unroll
    for (int it = 0; it < 8; it++) {
        float bm = NEG_BIG; int bi = 0x7fffffff;
        #pragma unroll
        for (int t = 0; t < 8; t++)
            if (v1[t] > bm) { bm = v1[t]; bi = t * 32 + lane; }
        #pragma unroll
        for (int off = 16; off > 0; off >>= 1) {
            float om = __shfl_xor_sync(0xffffffffu, bm, off);
            int   oi = __shfl_xor_sync(0xffffffffu, bi, off);
            if (om > bm || (om == bm && oi < bi)) { bm = om; bi = oi; }
        }
        tv1[it] = bm; ti1[it] = bi;
        if ((bi & 31) == lane) v1[bi >> 5] = NEG_BIG;
    }
    #pragma unroll
    for (int it = 0; it < 8; it++) {
        float bm = NEG_BIG; int bi = 0x7fffffff;
        #pragma unroll
        for (int t = 0; t < 8; t++)
            if (v2[t] > bm) { bm = v2[t]; bi = t * 32 + lane; }
        #pragma unroll
        for (int off = 16; off > 0; off >>= 1) {
            float om = __shfl_xor_sync(0xffffffffu, bm, off);
            int   oi = __shfl_xor_sync(0xffffffffu, bi, off);
            if (om > bm || (om == bm && oi < bi)) { bm = om; bi = oi; }
        }
        tv2[it] = bm; ti2[it] = bi;
        if ((bi & 31) == lane) v2[bi >> 5] = NEG_BIG;
    }

    // stage-2: 64 combos (ci = i*8 + j), top-4
    float cv[2];
    #pragma unroll
    for (int r = 0; r < 2; r++) {
        int ci = lane + r * 32;
        cv[r] = __fadd_rn(tv1[ci >> 3], tv2[ci & 7]);
    }
    float fs[4]; int fci[4];
    #pragma unroll
    for (int it = 0; it < 4; it++) {
        float bm; int bi;
        if (cv[0] >= cv[1]) { bm = cv[0]; bi = lane; }
        else                { bm = cv[1]; bi = lane + 32; }
        #pragma unroll
        for (int off = 16; off > 0; off >>= 1) {
            float om = __shfl_xor_sync(0xffffffffu, bm, off);
            int   oi = __shfl_xor_sync(0xffffffffu, bi, off);
            if (om > bm || (om == bm && oi < bi)) { bm = om; bi = oi; }
        }
        fs[it] = bm; fci[it] = bi;
        if ((bi & 31) == lane) cv[bi >> 5] = NEG_BIG;
    }

    if (lane == 0) {
        float m = fs[0];
        float e[4], sum = 0.0f;
        #pragma unroll
        for (int k = 0; k < 4; k++) { e[k] = expf(fs[k] - m); sum += e[k]; }
        float* out_scores  = out;
        float* out_experts = out + (size_t)N_TOK * H_HEADS * TOPK;
        #pragma unroll
        for (int k = 0; k < 4; k++) {
            int ci = fci[k];
            int i1 = ti1[ci >> 3];
            int i2 = ti2[ci & 7];
            out_scores [(size_t)gw * TOPK + k] = e[k] / sum;
            out_experts[(size_t)gw * TOPK + k] = (float)(i1 * S_KEYS + i2);
        }
    }
}

// -------------------- launch --------------------
extern "C" void kernel_launch(void* const* d_in, const int* in_sizes, int n_in,
                              void* d_out, int out_size)
{
    const float* x     = (const float*)d_in[0];   // [16384, 2048]
    const float* Wq    = (const float*)d_in[1];   // [4, 2048, 512]
    const float* bq    = (const float*)d_in[2];   // [4, 512]
    const float* gamma = (const float*)d_in[3];   // [4, 512]
    const float* beta  = (const float*)d_in[4];   // [4, 512]
    const float* K1    = (const float*)d_in[5];   // [256, 256]
    const float* K2    = (const float*)d_in[6];   // [256, 256]
    float* out = (float*)d_out;

    k_gemm_q<<<dim3(128, 16), 256>>>(x, Wq, bq);
    k_mean_part<<<dim3(256, NPART), 256>>>();
    k_mean_fin<<<8, 256>>>();
    k_var_part<<<dim3(256, NPART), 256>>>();
    k_var_fin<<<8, 256>>>();
    k_transpose<<<512, 256>>>(K1, K2);
    k_gemm_s<<<dim3(128, 2, 8), 512>>>(gamma, beta);
    k_topk<<<(N_TOK * H_HEADS * 32) / 256, 256>>>(out);
}

// round 8
// speedup vs baseline: 1.0312x; 1.0312x over previous
#include <cuda_runtime.h>
#include <math.h>

#define N_TOK   16384
#define D_MODEL 2048
#define Q_DIM   512
#define H_HEADS 4
#define HQ      2048      // H * Q
#define HALF    256       // Q/2
#define S_KEYS  256
#define TOPK    4
#define BN_EPS  1e-5f
#define NEG_BIG (-1e30f)
#define NPART   4         // row partials in stats reduction (XLA-style)
#define CHUNK   (N_TOK / NPART)   // 4096 rows per partial

// -------------------- device scratch (static, no allocation) --------------------
static __device__ float  g_q [(size_t)N_TOK * HQ];   // raw query projections [N, H*Q]
static __device__ float  g_s [(size_t)N_TOK * HQ];   // scores [N, H, 2, 256]
static __device__ float  g_pm[NPART][HQ];            // mean partials
static __device__ float  g_pv[NPART][HQ];            // var partials
static __device__ float  g_mun[HQ];                  // BN mean
static __device__ float  g_rn [HQ];                  // rsqrtf(var+eps)
static __device__ float  g_Kt [2 * HALF * S_KEYS];   // Kt[tbl][c][k] = K[k][c]

// -------------------- packed f32x2 helpers (each half = exact IEEE fp32 op) -----
__device__ __forceinline__ unsigned long long f2_pack(float lo, float hi) {
    unsigned long long r;
    asm("mov.b64 %0, {%1, %2};" : "=l"(r) : "f"(lo), "f"(hi));
    return r;
}
__device__ __forceinline__ void f2_unpack(unsigned long long v, float& lo, float& hi) {
    asm("mov.b64 {%0, %1}, %2;" : "=f"(lo), "=f"(hi) : "l"(v));
}
__device__ __forceinline__ unsigned long long f2_fma(
    unsigned long long a, unsigned long long b, unsigned long long c) {
    unsigned long long d;
    asm("fma.rn.f32x2 %0, %1, %2, %3;" : "=l"(d) : "l"(a), "l"(b), "l"(c));
    return d;
}

// =====================================================================
// Kernel 1: q = x @ Wq + bq.  128x128 tile, BK=16, 256 thr, 8x8/thread.
// ASCENDING k, single FMA chain per accumulator — bitwise identical to
// the R7 pass; inner loop uses packed fma.rn.f32x2 (2 independent IEEE
// fp32 FMAs per instruction, accumulator pairs along adjacent columns,
// chains never mix) for 2x fp32 throughput.
// =====================================================================
__global__ __launch_bounds__(256) void k_gemm_q(
    const float* __restrict__ x, const float* __restrict__ Wq, const float* __restrict__ bq)
{
    __shared__ float As[16][128];
    __shared__ float Bs[16][128];

    const int tid = threadIdx.x;          // 0..255
    const int tx  = tid & 15;             // col group: 8 cols each
    const int ty  = tid >> 4;             // row group: 8 rows each

    const int rowTile = blockIdx.x;       // 0..127
    const int colTile = blockIdx.y;       // 0..15
    const int head    = colTile >> 2;
    const int cih     = (colTile & 3) * 128;

    const float* A = x  + (size_t)rowTile * 128 * D_MODEL;
    const float* B = Wq + (size_t)head * D_MODEL * Q_DIM + cih;

    unsigned long long acc2[8][4];        // [row][col-pair]
    #pragma unroll
    for (int i = 0; i < 8; i++)
        #pragma unroll
        for (int m = 0; m < 4; m++) acc2[i][m] = 0ull;

    int a_r[2], a_c[2], b_r[2], b_c[2];
    #pragma unroll
    for (int i = 0; i < 2; i++) {
        int id = tid + i * 256;           // 0..511
        a_r[i] = id >> 2;                 // A row 0..127
        a_c[i] = (id & 3) * 4;            // A k 0,4,8,12
        b_r[i] = id >> 5;                 // B k 0..15
        b_c[i] = (id & 31) * 4;           // B col
    }

    float4 pa[2], pb[2];
    int kt = 0;
    #pragma unroll
    for (int i = 0; i < 2; i++) {
        pa[i] = *(const float4*)(A + (size_t)a_r[i] * D_MODEL + kt + a_c[i]);
        pb[i] = *(const float4*)(B + (size_t)(kt + b_r[i]) * Q_DIM + b_c[i]);
    }

    while (kt < D_MODEL) {
        #pragma unroll
        for (int i = 0; i < 2; i++) {
            As[a_c[i] + 0][a_r[i]] = pa[i].x;
            As[a_c[i] + 1][a_r[i]] = pa[i].y;
            As[a_c[i] + 2][a_r[i]] = pa[i].z;
            As[a_c[i] + 3][a_r[i]] = pa[i].w;
            *(float4*)(&Bs[b_r[i]][b_c[i]]) = pb[i];
        }
        __syncthreads();

        int ktn = kt + 16;
        if (ktn < D_MODEL) {
            #pragma unroll
            for (int i = 0; i < 2; i++) {
                pa[i] = *(const float4*)(A + (size_t)a_r[i] * D_MODEL + ktn + a_c[i]);
                pb[i] = *(const float4*)(B + (size_t)(ktn + b_r[i]) * Q_DIM + b_c[i]);
            }
        }

        #pragma unroll
        for (int k = 0; k < 16; k++) {
            unsigned long long a2[8], b2[4];
            #pragma unroll
            for (int i = 0; i < 8; i++) {
                float av = As[k][ty * 8 + i];
                a2[i] = f2_pack(av, av);
            }
            #pragma unroll
            for (int m = 0; m < 4; m++)     // adjacent col pair, 8B-aligned smem read
                b2[m] = *(const unsigned long long*)(&Bs[k][tx * 8 + m * 2]);
            #pragma unroll
            for (int i = 0; i < 8; i++)
                #pragma unroll
                for (int m = 0; m < 4; m++)
                    acc2[i][m] = f2_fma(a2[i], b2[m], acc2[i][m]);
        }
        __syncthreads();
        kt = ktn;
    }

    float* C = g_q + (size_t)rowTile * 128 * HQ + colTile * 128;
    const float* bias = bq + head * Q_DIM + cih;
    #pragma unroll
    for (int i = 0; i < 8; i++) {
        int r = ty * 8 + i;
        #pragma unroll
        for (int m = 0; m < 4; m++) {
            float lo, hi;
            f2_unpack(acc2[i][m], lo, hi);
            int c = tx * 8 + m * 2;
            C[(size_t)r * HQ + c + 0] = lo + bias[c + 0];
            C[(size_t)r * HQ + c + 1] = hi + bias[c + 1];
        }
    }
}

// =====================================================================
// Kernel 2a: MEAN partials. Same arithmetic as the R7 pass: per (c,lane)
// fp32 chain over rows b*4096 + lane + 32*j (j ascending), shfl-down
// tree 16..1. Memory access restructured: 32x32 tiles staged through
// smem so gmem reads are fully coalesced (one 128B line per warp-load).
// Block: 256 thr = 8 warps, 32 columns (4 per warp), grid (64, NPART).
// =====================================================================
__global__ __launch_bounds__(256) void k_mean_part()
{
    __shared__ float sm[32][33];          // +1 pad: lane-major reads conflict-free
    const int c0 = blockIdx.x * 32;
    const int b  = blockIdx.y;
    const int w  = threadIdx.x >> 5;
    const int l  = threadIdx.x & 31;

    float acc[4] = {0.f, 0.f, 0.f, 0.f};
    const float* base = g_q + (size_t)b * CHUNK * HQ + c0;

    for (int j = 0; j < CHUNK / 32; j++) {
        #pragma unroll
        for (int i = 0; i < 4; i++) {
            int e = threadIdx.x + 256 * i;      // warp covers one row's 32 cols
            int r = e >> 5, cc = e & 31;
            sm[r][cc] = base[(size_t)(j * 32 + r) * HQ + cc];
        }
        __syncthreads();
        #pragma unroll
        for (int i = 0; i < 4; i++)
            acc[i] = __fadd_rn(acc[i], sm[l][w * 4 + i]);
        __syncthreads();
    }
    #pragma unroll
    for (int i = 0; i < 4; i++) {
        float s = acc[i];
        #pragma unroll
        for (int off = 16; off > 0; off >>= 1)
            s = __fadd_rn(s, __shfl_down_sync(0xffffffffu, s, off));
        if (l == 0) g_pm[b][c0 + w * 4 + i] = s;
    }
}

__global__ __launch_bounds__(256) void k_mean_fin()
{
    int c = blockIdx.x * 256 + threadIdx.x;
    float s = g_pm[0][c];
    #pragma unroll
    for (int b = 1; b < NPART; b++) s = __fadd_rn(s, g_pm[b][c]);
    g_mun[c] = s * (1.0f / (float)N_TOK);   // /2^14 exact
}

// =====================================================================
// Kernel 2b: VAR partials via mean((x-mu)^2), identical arithmetic to
// the R7 pass (explicit sub/mul/add, no FMA contraction), coalesced
// tile staging as in k_mean_part.
// =====================================================================
__global__ __launch_bounds__(256) void k_var_part()
{
    __shared__ float sm[32][33];
    const int c0 = blockIdx.x * 32;
    const int b  = blockIdx.y;
    const int w  = threadIdx.x >> 5;
    const int l  = threadIdx.x & 31;

    float mu[4], acc[4] = {0.f, 0.f, 0.f, 0.f};
    #pragma unroll
    for (int i = 0; i < 4; i++) mu[i] = g_mun[c0 + w * 4 + i];

    const float* base = g_q + (size_t)b * CHUNK * HQ + c0;

    for (int j = 0; j < CHUNK / 32; j++) {
        #pragma unroll
        for (int i = 0; i < 4; i++) {
            int e = threadIdx.x + 256 * i;
            int r = e >> 5, cc = e & 31;
            sm[r][cc] = base[(size_t)(j * 32 + r) * HQ + cc];
        }
        __syncthreads();
        #pragma unroll
        for (int i = 0; i < 4; i++) {
            float d = __fsub_rn(sm[l][w * 4 + i], mu[i]);
            acc[i] = __fadd_rn(acc[i], __fmul_rn(d, d));
        }
        __syncthreads();
    }
    #pragma unroll
    for (int i = 0; i < 4; i++) {
        float s = acc[i];
        #pragma unroll
        for (int off = 16; off > 0; off >>= 1)
            s = __fadd_rn(s, __shfl_down_sync(0xffffffffu, s, off));
        if (l == 0) g_pv[b][c0 + w * 4 + i] = s;
    }
}

__global__ __launch_bounds__(256) void k_var_fin()
{
    int c = blockIdx.x * 256 + threadIdx.x;
    float s = g_pv[0][c];
    #pragma unroll
    for (int b = 1; b < NPART; b++) s = __fadd_rn(s, g_pv[b][c]);
    float var = s * (1.0f / (float)N_TOK);
    g_rn[c] = rsqrtf(__fadd_rn(var, BN_EPS));
}

// =====================================================================
// Kernel 3: transpose key tables. Kt[tbl][c][k] = K[k][c].
// =====================================================================
__global__ __launch_bounds__(256) void k_transpose(
    const float* __restrict__ K1, const float* __restrict__ K2)
{
    int idx = blockIdx.x * 256 + threadIdx.x;     // 0 .. 2*256*256-1
    int tbl = idx >> 16;
    int c   = (idx >> 8) & 255;
    int k   = idx & 255;
    const float* Ksrc = tbl ? K2 : K1;
    g_Kt[idx] = Ksrc[k * HALF + c];
}

// =====================================================================
// Kernel 4: scoring GEMM  s = normalize(q) @ Kt.
// Normalization on A-tile load, exact reference elementwise order
// (identical to R7). Ascending-k single FMA chain; inner loop packed
// f32x2 (bitwise-identical halves). 512 thr, 4x8/thread.
// =====================================================================
__global__ __launch_bounds__(512) void k_gemm_s(
    const float* __restrict__ gamma, const float* __restrict__ beta)
{
    __shared__ float As[16][128];
    __shared__ float Bs[16][128];

    const int tid = threadIdx.x;
    const int tx  = tid & 15;
    const int ty  = tid >> 4;

    const int z   = blockIdx.z;     // 0..7
    const int tbl = z >> 2;
    const int h   = z & 3;
    const int cb  = h * Q_DIM + tbl * HALF;

    const float* A  = g_q + (size_t)blockIdx.x * 128 * HQ + cb;
    const float* B  = g_Kt + (size_t)tbl * HALF * S_KEYS + blockIdx.y * 128;
    const float* mu = g_mun + cb;
    const float* rn = g_rn  + cb;
    const float* gm = gamma + cb;
    const float* bt = beta  + cb;

    unsigned long long acc2[4][4];
    #pragma unroll
    for (int i = 0; i < 4; i++)
        #pragma unroll
        for (int m = 0; m < 4; m++) acc2[i][m] = 0ull;

    const int ar = tid >> 2;
    const int ac = (tid & 3) * 4;
    const int br = tid >> 5;
    const int bc = (tid & 31) * 4;

    for (int kt = 0; kt < HALF; kt += 16) {
        float4 va = *(const float4*)(A + (size_t)ar * HQ + kt + ac);
        int c0 = kt + ac;
        va.x = __fmul_rn(__fsub_rn(va.x, mu[c0 + 0]), rn[c0 + 0]) * gm[c0 + 0] + bt[c0 + 0];
        va.y = __fmul_rn(__fsub_rn(va.y, mu[c0 + 1]), rn[c0 + 1]) * gm[c0 + 1] + bt[c0 + 1];
        va.z = __fmul_rn(__fsub_rn(va.z, mu[c0 + 2]), rn[c0 + 2]) * gm[c0 + 2] + bt[c0 + 2];
        va.w = __fmul_rn(__fsub_rn(va.w, mu[c0 + 3]), rn[c0 + 3]) * gm[c0 + 3] + bt[c0 + 3];
        As[ac + 0][ar] = va.x; As[ac + 1][ar] = va.y;
        As[ac + 2][ar] = va.z; As[ac + 3][ar] = va.w;
        *(float4*)(&Bs[br][bc]) = *(const float4*)(B + (size_t)(kt + br) * S_KEYS + bc);
        __syncthreads();

        #pragma unroll
        for (int k = 0; k < 16; k++) {
            unsigned long long a2[4], b2[4];
            #pragma unroll
            for (int i = 0; i < 4; i++) {
                float av = As[k][ty * 4 + i];
                a2[i] = f2_pack(av, av);
            }
            #pragma unroll
            for (int m = 0; m < 4; m++)
                b2[m] = *(const unsigned long long*)(&Bs[k][tx * 8 + m * 2]);
            #pragma unroll
            for (int i = 0; i < 4; i++)
                #pragma unroll
                for (int m = 0; m < 4; m++)
                    acc2[i][m] = f2_fma(a2[i], b2[m], acc2[i][m]);
        }
        __syncthreads();
    }

    float* C = g_s + (size_t)blockIdx.x * 128 * HQ + cb + blockIdx.y * 128;
    #pragma unroll
    for (int i = 0; i < 4; i++) {
        int r = ty * 4 + i;
        #pragma unroll
        for (int m = 0; m < 4; m++) {
            float lo, hi;
            f2_unpack(acc2[i][m], lo, hi);
            int c = tx * 8 + m * 2;
            C[(size_t)r * HQ + c + 0] = lo;
            C[(size_t)r * HQ + c + 1] = hi;
        }
    }
}

// =====================================================================
// Kernel 5: per-(n,h) two-stage top-k + softmax. One warp per row.
// Ties break to lower index (matching jax.lax.top_k). Unchanged from R7.
// =====================================================================
__global__ __launch_bounds__(256) void k_topk(float* __restrict__ out)
{
    int gw   = (blockIdx.x * blockDim.x + threadIdx.x) >> 5;  // n*H + h
    int lane = threadIdx.x & 31;
    if (gw >= N_TOK * H_HEADS) return;
    int n = gw >> 2;
    int h = gw & 3;

    const float* s1 = g_s + (size_t)n * HQ + h * Q_DIM;
    const float* s2 = s1 + HALF;

    float v1[8], v2[8];
    #pragma unroll
    for (int t = 0; t < 8; t++) { v1[t] = s1[t * 32 + lane]; v2[t] = s2[t * 32 + lane]; }

    float tv1[8], tv2[8];
    int   ti1[8], ti2[8];

    #pragma unroll
    for (int it = 0; it < 8; it++) {
        float bm = NEG_BIG; int bi = 0x7fffffff;
        #pragma unroll
        for (int t = 0; t < 8; t++)
            if (v1[t] > bm) { bm = v1[t]; bi = t * 32 + lane; }
        #pragma unroll
        for (int off = 16; off > 0; off >>= 1) {
            float om = __shfl_xor_sync(0xffffffffu, bm, off);
            int   oi = __shfl_xor_sync(0xffffffffu, bi, off);
            if (om > bm || (om == bm && oi < bi)) { bm = om; bi = oi; }
        }
        tv1[it] = bm; ti1[it] = bi;
        if ((bi & 31) == lane) v1[bi >> 5] = NEG_BIG;
    }
    #pragma unroll
    for (int it = 0; it < 8; it++) {
        float bm = NEG_BIG; int bi = 0x7fffffff;
        #pragma unroll
        for (int t = 0; t < 8; t++)
            if (v2[t] > bm) { bm = v2[t]; bi = t * 32 + lane; }
        #pragma unroll
        for (int off = 16; off > 0; off >>= 1) {
            float om = __shfl_xor_sync(0xffffffffu, bm, off);
            int   oi = __shfl_xor_sync(0xffffffffu, bi, off);
            if (om > bm || (om == bm && oi < bi)) { bm = om; bi = oi; }
        }
        tv2[it] = bm; ti2[it] = bi;
        if ((bi & 31) == lane) v2[bi >> 5] = NEG_BIG;
    }

    // stage-2: 64 combos (ci = i*8 + j), top-4
    float cv[2];
    #pragma unroll
    for (int r = 0; r < 2; r++) {
        int ci = lane + r * 32;
        cv[r] = __fadd_rn(tv1[ci >> 3], tv2[ci & 7]);
    }
    float fs[4]; int fci[4];
    #pragma unroll
    for (int it = 0; it < 4; it++) {
        float bm; int bi;
        if (cv[0] >= cv[1]) { bm = cv[0]; bi = lane; }
        else                { bm = cv[1]; bi = lane + 32; }
        #pragma unroll
        for (int off = 16; off > 0; off >>= 1) {
            float om = __shfl_xor_sync(0xffffffffu, bm, off);
            int   oi = __shfl_xor_sync(0xffffffffu, bi, off);
            if (om > bm || (om == bm && oi < bi)) { bm = om; bi = oi; }
        }
        fs[it] = bm; fci[it] = bi;
        if ((bi & 31) == lane) cv[bi >> 5] = NEG_BIG;
    }

    if (lane == 0) {
        float m = fs[0];
        float e[4], sum = 0.0f;
        #pragma unroll
        for (int k = 0; k < 4; k++) { e[k] = expf(fs[k] - m); sum += e[k]; }
        float* out_scores  = out;
        float* out_experts = out + (size_t)N_TOK * H_HEADS * TOPK;
        #pragma unroll
        for (int k = 0; k < 4; k++) {
            int ci = fci[k];
            int i1 = ti1[ci >> 3];
            int i2 = ti2[ci & 7];
            out_scores [(size_t)gw * TOPK + k] = e[k] / sum;
            out_experts[(size_t)gw * TOPK + k] = (float)(i1 * S_KEYS + i2);
        }
    }
}

// -------------------- launch --------------------
extern "C" void kernel_launch(void* const* d_in, const int* in_sizes, int n_in,
                              void* d_out, int out_size)
{
    const float* x     = (const float*)d_in[0];   // [16384, 2048]
    const float* Wq    = (const float*)d_in[1];   // [4, 2048, 512]
    const float* bq    = (const float*)d_in[2];   // [4, 512]
    const float* gamma = (const float*)d_in[3];   // [4, 512]
    const float* beta  = (const float*)d_in[4];   // [4, 512]
    const float* K1    = (const float*)d_in[5];   // [256, 256]
    const float* K2    = (const float*)d_in[6];   // [256, 256]
    float* out = (float*)d_out;

    k_gemm_q<<<dim3(128, 16), 256>>>(x, Wq, bq);
    k_mean_part<<<dim3(64, NPART), 256>>>();
    k_mean_fin<<<8, 256>>>();
    k_var_part<<<dim3(64, NPART), 256>>>();
    k_var_fin<<<8, 256>>>();
    k_transpose<<<512, 256>>>(K1, K2);
    k_gemm_s<<<dim3(128, 2, 8), 512>>>(gamma, beta);
    k_topk<<<(N_TOK * H_HEADS * 32) / 256, 256>>>(out);
}